// round 1
// baseline (speedup 1.0000x reference)
#include <cuda_runtime.h>
#include <math.h>

#define NN 50000
#define NE 800000
#define INC 128
#define D 64

// ---------------- scratch (static device globals; no allocation) ------------
__device__ float g_vq[INC];          // weight_n @ (query @ att_w[:d])
__device__ float g_vk[INC];          // weight_n @ (key_w @ att_w[d:2d])
__device__ float g_ce;               // weight_e[0,:] . att_w[2d:]
__device__ float g_W1[INC * D];      // weight_n @ out_w[:d]
__device__ float g_hsrc[(size_t)NN * D];
__device__ float g_qa[NN];
__device__ float g_ka[NN];
__device__ float g_logits[NE];       // logits, then overwritten with exp(l - m)
__device__ float g_agg[(size_t)NN * D];
__device__ int   g_start[NN + 1];

// ---------------- K_pre: fold small matrices (1 block) ----------------------
__global__ void k_pre(const float* __restrict__ weight_n,
                      const float* __restrict__ weight_e,
                      const float* __restrict__ query,
                      const float* __restrict__ key_w,
                      const float* __restrict__ att_w,
                      const float* __restrict__ out_w) {
    __shared__ float s_aw[3 * D];
    __shared__ float s_tq[D], s_tk[D];
    __shared__ float s_ow[D * D];   // out_w rows [0,64)
    int t = threadIdx.x;            // 256 threads
    for (int i = t; i < 3 * D; i += 256) s_aw[i] = att_w[i];
    for (int i = t; i < D * D; i += 256) s_ow[i] = out_w[i];
    __syncthreads();
    if (t < D) {
        float sq = 0.f, sk = 0.f;
        for (int j = 0; j < D; j++) {
            sq += query[t * D + j] * s_aw[j];
            sk += key_w[t * D + j] * s_aw[D + j];
        }
        s_tq[t] = sq; s_tk[t] = sk;
    }
    if (t == 0) {
        float c = 0.f;
        for (int j = 0; j < D; j++) c += weight_e[j] * s_aw[2 * D + j];
        g_ce = c;
    }
    __syncthreads();
    if (t < INC) {
        float vq = 0.f, vk = 0.f;
        for (int i = 0; i < D; i++) {
            float w = weight_n[t * D + i];
            vq += w * s_tq[i];
            vk += w * s_tk[i];
        }
        g_vq[t] = vq; g_vk[t] = vk;
    }
    // W1[k][c] = sum_j weight_n[k][j] * out_w[j][c]   (j < 64)
    for (int idx = t; idx < INC * D; idx += 256) {
        int k = idx >> 6, c = idx & 63;
        float s = 0.f;
        #pragma unroll 8
        for (int j = 0; j < D; j++) s += weight_n[k * D + j] * s_ow[j * D + c];
        g_W1[idx] = s;
    }
}

// ---------------- K_qk: per-node attention scalars (warp per node) ----------
__global__ void k_qk(const float* __restrict__ feat_src,
                     const float* __restrict__ feat_dst, int n_nodes) {
    int warp = (blockIdx.x * blockDim.x + threadIdx.x) >> 5;
    int lane = threadIdx.x & 31;
    if (warp >= n_nodes) return;
    const float* fs = feat_src + (size_t)warp * INC;
    const float* fd = feat_dst + (size_t)warp * INC;
    float qa = 0.f, ka = 0.f;
    #pragma unroll
    for (int j = 0; j < INC; j += 32) {
        qa += fd[j + lane] * g_vq[j + lane];
        ka += fs[j + lane] * g_vk[j + lane];
    }
    #pragma unroll
    for (int o = 16; o > 0; o >>= 1) {
        qa += __shfl_down_sync(0xffffffffu, qa, o);
        ka += __shfl_down_sync(0xffffffffu, ka, o);
    }
    if (lane == 0) { g_qa[warp] = qa; g_ka[warp] = ka; }
}

// ---------------- K_hsrc: h_src = feat_src @ weight_n (tiled GEMM) ----------
// 64 rows per block, 256 threads, 4x4 register tile, smem A(64x128)+W(128x64)
__global__ void k_hsrc(const float* __restrict__ feat,
                       const float* __restrict__ weight_n, int n_rows) {
    extern __shared__ float sm[];
    float* As = sm;               // 64 * 128
    float* Ws = sm + 64 * INC;    // 128 * 64
    int row0 = blockIdx.x * 64;
    int t = threadIdx.x;
    for (int i = t; i < INC * D; i += 256) Ws[i] = weight_n[i];
    int nr = n_rows - row0; if (nr > 64) nr = 64;
    int limit4 = nr * (INC / 4);
    const float4* f4 = (const float4*)(feat + (size_t)row0 * INC);
    float4* A4 = (float4*)As;
    for (int i = t; i < 64 * (INC / 4); i += 256)
        A4[i] = (i < limit4) ? f4[i] : make_float4(0.f, 0.f, 0.f, 0.f);
    __syncthreads();
    int tx = t & 15, ty = t >> 4;
    int r0 = ty * 4, c0 = tx * 4;
    float acc[4][4] = {};
    #pragma unroll 4
    for (int k = 0; k < INC; k++) {
        float a0 = As[(r0 + 0) * INC + k];
        float a1 = As[(r0 + 1) * INC + k];
        float a2 = As[(r0 + 2) * INC + k];
        float a3 = As[(r0 + 3) * INC + k];
        float4 b = *(const float4*)&Ws[k * D + c0];
        acc[0][0] += a0 * b.x; acc[0][1] += a0 * b.y; acc[0][2] += a0 * b.z; acc[0][3] += a0 * b.w;
        acc[1][0] += a1 * b.x; acc[1][1] += a1 * b.y; acc[1][2] += a1 * b.z; acc[1][3] += a1 * b.w;
        acc[2][0] += a2 * b.x; acc[2][1] += a2 * b.y; acc[2][2] += a2 * b.z; acc[2][3] += a2 * b.w;
        acc[3][0] += a3 * b.x; acc[3][1] += a3 * b.y; acc[3][2] += a3 * b.z; acc[3][3] += a3 * b.w;
    }
    #pragma unroll
    for (int i = 0; i < 4; i++) {
        int r = row0 + r0 + i;
        if (r < n_rows)
            *(float4*)&g_hsrc[(size_t)r * D + c0] =
                make_float4(acc[i][0], acc[i][1], acc[i][2], acc[i][3]);
    }
}

// ---------------- K_bounds: segment starts via binary search ----------------
__global__ void k_bounds(const int* __restrict__ dst_idx, int n_nodes, int n_edges) {
    int n = blockIdx.x * blockDim.x + threadIdx.x;
    if (n > n_nodes) return;
    int lo = 0, hi = n_edges;
    while (lo < hi) {
        int mid = (lo + hi) >> 1;
        if (dst_idx[mid] < n) lo = mid + 1; else hi = mid;
    }
    g_start[n] = lo;
}

// ---------------- K_logits: per-edge attention logits -----------------------
__global__ void k_logits(const float* __restrict__ ew,
                         const int* __restrict__ src,
                         const int* __restrict__ dst,
                         const float* __restrict__ att_b, int n_edges) {
    int e = blockIdx.x * blockDim.x + threadIdx.x;
    if (e >= n_edges) return;
    float x = g_qa[dst[e]] + g_ka[src[e]] + ew[e] * g_ce + att_b[0];
    g_logits[e] = (x >= 0.f) ? x : 0.2f * x;
}

// ---------------- K_agg: segment softmax + weighted message sum -------------
// warp per destination node; edges contiguous because dst_idx is sorted
__global__ void k_agg(const int* __restrict__ src_idx, int n_nodes) {
    int warp = (blockIdx.x * blockDim.x + threadIdx.x) >> 5;
    int lane = threadIdx.x & 31;
    if (warp >= n_nodes) return;
    int e0 = g_start[warp], e1 = g_start[warp + 1];
    float2* aggp = (float2*)&g_agg[(size_t)warp * D];
    if (e0 == e1) { aggp[lane] = make_float2(0.f, 0.f); return; }
    float m = -INFINITY;
    for (int e = e0 + lane; e < e1; e += 32) m = fmaxf(m, g_logits[e]);
    #pragma unroll
    for (int o = 16; o > 0; o >>= 1) m = fmaxf(m, __shfl_xor_sync(0xffffffffu, m, o));
    float s = 0.f;
    for (int e = e0 + lane; e < e1; e += 32) {
        float w = __expf(g_logits[e] - m);
        g_logits[e] = w;          // overwrite logits with unnormalized weights
        s += w;
    }
    #pragma unroll
    for (int o = 16; o > 0; o >>= 1) s += __shfl_xor_sync(0xffffffffu, s, o);
    __syncwarp();                  // make lane-strided g_logits writes visible
    float inv = 1.f / (s + 1e-16f);
    float2 acc = make_float2(0.f, 0.f);
    for (int e = e0; e < e1; e++) {
        float alpha = g_logits[e] * inv;            // broadcast load
        int sidx = src_idx[e];                      // broadcast load
        float2 h = *(const float2*)&g_hsrc[(size_t)sidx * D + 2 * lane];
        acc.x += alpha * h.x;
        acc.y += alpha * h.y;
    }
    aggp[lane] = acc;
}

// ---------------- K_out: out = feat_dst@W1 + agg@out_w2 + b (K=192 GEMM) ----
__global__ void k_out(const float* __restrict__ feat_dst,
                      const float* __restrict__ out_w,
                      const float* __restrict__ out_b,
                      float* __restrict__ out, int n_rows) {
    extern __shared__ float sm[];
    const int KK = INC + D;        // 192
    float* As = sm;                // 64 * 192
    float* Ws = sm + 64 * KK;      // 192 * 64
    int row0 = blockIdx.x * 64;
    int t = threadIdx.x;
    for (int i = t; i < INC * D; i += 256) Ws[i] = g_W1[i];
    for (int i = t; i < D * D; i += 256) Ws[INC * D + i] = out_w[D * D + i];
    int nr = n_rows - row0; if (nr > 64) nr = 64;
    for (int i = t; i < 64 * (INC / 4); i += 256) {
        int r = i / (INC / 4), c4 = i % (INC / 4);
        float4 v = (r < nr) ? ((const float4*)(feat_dst + (size_t)(row0 + r) * INC))[c4]
                            : make_float4(0.f, 0.f, 0.f, 0.f);
        ((float4*)&As[r * KK])[c4] = v;
    }
    for (int i = t; i < 64 * (D / 4); i += 256) {
        int r = i / (D / 4), c4 = i % (D / 4);
        float4 v = (r < nr) ? ((const float4*)&g_agg[(size_t)(row0 + r) * D])[c4]
                            : make_float4(0.f, 0.f, 0.f, 0.f);
        ((float4*)&As[r * KK + INC])[c4] = v;
    }
    __syncthreads();
    int tx = t & 15, ty = t >> 4;
    int r0 = ty * 4, c0 = tx * 4;
    float4 bias = *(const float4*)&out_b[c0];
    float acc[4][4];
    #pragma unroll
    for (int i = 0; i < 4; i++) {
        acc[i][0] = bias.x; acc[i][1] = bias.y; acc[i][2] = bias.z; acc[i][3] = bias.w;
    }
    #pragma unroll 4
    for (int k = 0; k < KK; k++) {
        float a0 = As[(r0 + 0) * KK + k];
        float a1 = As[(r0 + 1) * KK + k];
        float a2 = As[(r0 + 2) * KK + k];
        float a3 = As[(r0 + 3) * KK + k];
        float4 b = *(const float4*)&Ws[k * D + c0];
        acc[0][0] += a0 * b.x; acc[0][1] += a0 * b.y; acc[0][2] += a0 * b.z; acc[0][3] += a0 * b.w;
        acc[1][0] += a1 * b.x; acc[1][1] += a1 * b.y; acc[1][2] += a1 * b.z; acc[1][3] += a1 * b.w;
        acc[2][0] += a2 * b.x; acc[2][1] += a2 * b.y; acc[2][2] += a2 * b.z; acc[2][3] += a2 * b.w;
        acc[3][0] += a3 * b.x; acc[3][1] += a3 * b.y; acc[3][2] += a3 * b.z; acc[3][3] += a3 * b.w;
    }
    #pragma unroll
    for (int i = 0; i < 4; i++) {
        int r = row0 + r0 + i;
        if (r < n_rows)
            *(float4*)&out[(size_t)r * D + c0] =
                make_float4(acc[i][0], acc[i][1], acc[i][2], acc[i][3]);
    }
}

// ---------------------------------------------------------------------------
extern "C" void kernel_launch(void* const* d_in, const int* in_sizes, int n_in,
                              void* d_out, int out_size) {
    const float* feat_src    = (const float*)d_in[0];
    const float* feat_dst    = (const float*)d_in[1];
    const float* edge_weight = (const float*)d_in[2];
    const int*   src_idx     = (const int*)d_in[3];
    const int*   dst_idx     = (const int*)d_in[4];
    const float* weight_n    = (const float*)d_in[5];
    const float* weight_e    = (const float*)d_in[6];
    const float* query       = (const float*)d_in[7];
    const float* key_w       = (const float*)d_in[8];
    const float* att_w       = (const float*)d_in[9];
    const float* att_b       = (const float*)d_in[10];
    const float* out_w       = (const float*)d_in[11];
    const float* out_b       = (const float*)d_in[12];
    float* out = (float*)d_out;

    int n_nodes = in_sizes[0] / INC;
    int n_edges = in_sizes[3];

    const int SMEM_HSRC = (64 * INC + INC * D) * 4;          // 64 KB
    const int SMEM_OUT  = (64 * (INC + D) + (INC + D) * D) * 4; // 96 KB
    cudaFuncSetAttribute(k_hsrc, cudaFuncAttributeMaxDynamicSharedMemorySize, SMEM_HSRC);
    cudaFuncSetAttribute(k_out,  cudaFuncAttributeMaxDynamicSharedMemorySize, SMEM_OUT);

    k_pre<<<1, 256>>>(weight_n, weight_e, query, key_w, att_w, out_w);
    k_qk<<<(n_nodes * 32 + 255) / 256, 256>>>(feat_src, feat_dst, n_nodes);
    k_hsrc<<<(n_nodes + 63) / 64, 256, SMEM_HSRC>>>(feat_src, weight_n, n_nodes);
    k_bounds<<<(n_nodes + 1 + 255) / 256, 256>>>(dst_idx, n_nodes, n_edges);
    k_logits<<<(n_edges + 255) / 256, 256>>>(edge_weight, src_idx, dst_idx, att_b, n_edges);
    k_agg<<<(n_nodes * 32 + 255) / 256, 256>>>(src_idx, n_nodes);
    k_out<<<(n_nodes + 63) / 64, 256, SMEM_OUT>>>(feat_dst, out_w, out_b, out, n_nodes);
}